// round 14
// baseline (speedup 1.0000x reference)
#include <cuda_runtime.h>
#include <cuda_fp16.h>
#include <cstdint>
#include <cstddef>
#include <math.h>

#define BB    256
#define HH    128
#define NNODE 1000
#define NPAD  1024
#define K3    384
#define KC    64          // k per chunk (4 x k16 steps)
#define NCH   (K3 / KC)   // 6
#define NT    64          // n per CTA
#define NTILES (NPAD / NT) // 16 CTAs per batch
#define APAD  72          // As row stride (fp16)
#define BPAD  72          // Bs row stride (fp16)

#define AS1   (HH * APAD)     // 9216 halfs per A buffer
#define BS1   (KC * BPAD)     // 4608 halfs per Bs buffer

// ---------------- scratch (__device__ globals) -----------------------------
__device__ float g_dvec[BB * HH];
__device__ float g_attn[BB * NPAD];
__device__ __half g_whi[HH * K3];
__device__ int   g_cnt[BB];              // zero-init; reset after use (graph-safe)

// ---------------- helpers --------------------------------------------------
__device__ __forceinline__ uint32_t smem_u32(const void* p) {
    uint32_t a;
    asm("{ .reg .u64 t; cvta.to.shared.u64 t, %1; cvt.u32.u64 %0, t; }" : "=r"(a) : "l"(p));
    return a;
}
#define CP16(dst, src) \
    asm volatile("cp.async.cg.shared.global [%0], [%1], 16;" :: "r"(dst), "l"(src))
#define CP_COMMIT() asm volatile("cp.async.commit_group;")
#define CP_WAIT(n)  asm volatile("cp.async.wait_group %0;" :: "n"(n))

__device__ __forceinline__ void ldsm_x4(uint32_t& r0, uint32_t& r1,
                                        uint32_t& r2, uint32_t& r3, uint32_t a) {
    asm volatile("ldmatrix.sync.aligned.m8n8.x4.shared.b16 {%0,%1,%2,%3}, [%4];"
                 : "=r"(r0), "=r"(r1), "=r"(r2), "=r"(r3) : "r"(a));
}
__device__ __forceinline__ void ldsm_x4_t(uint32_t& r0, uint32_t& r1,
                                          uint32_t& r2, uint32_t& r3, uint32_t a) {
    asm volatile("ldmatrix.sync.aligned.m8n8.x4.trans.shared.b16 {%0,%1,%2,%3}, [%4];"
                 : "=r"(r0), "=r"(r1), "=r"(r2), "=r"(r3) : "r"(a));
}
__device__ __forceinline__ void mma16816(float* c, const uint32_t* a,
                                         uint32_t b0, uint32_t b1) {
    asm volatile("mma.sync.aligned.m16n8k16.row.col.f32.f16.f16.f32 "
                 "{%0,%1,%2,%3}, {%4,%5,%6,%7}, {%8,%9}, {%0,%1,%2,%3};"
                 : "+f"(c[0]), "+f"(c[1]), "+f"(c[2]), "+f"(c[3])
                 : "r"(a[0]), "r"(a[1]), "r"(a[2]), "r"(a[3]), "r"(b0), "r"(b1));
}
// fp32x4 -> packed fp16x4
__device__ __forceinline__ unsigned long long cvt4h(float4 f) {
    __half2 p0 = __floats2half2_rn(f.x, f.y);
    __half2 p1 = __floats2half2_rn(f.z, f.w);
    union { __half2 h[2]; unsigned long long u; } r;
    r.h[0] = p0; r.h[1] = p1;
    return r.u;
}
__device__ __forceinline__ float tanh_fast(float x) {
    float t = __expf(2.f * x);
    return 1.f - __fdividef(2.f, t + 1.f);
}

// SMEM layout (bytes)
#define SO_A    0                              // 3 x AS1 fp16 = 55296
#define SO_BS   (SO_A + 3 * AS1 * 2)           // 55296: 2 x BS1 fp16 = 18432
#define SO_RED  (SO_BS + 2 * BS1 * 2)          // 73728: 4*64 fp32 = 1024
#define SO_SMX  (SO_RED + 4 * NT * 4)          // 74752: 256 fp32 = 1024
#define SMEM_SZ (SO_SMX + 256 * 4)             // 75776  (x3 CTA = 227.3KB)

// ---------------------------------------------------------------------------
// Prep kernel: CTAs [0,128) pack W -> fp16; CTAs [128,384) dvec
// ---------------------------------------------------------------------------
__global__ void __launch_bounds__(HH) prep_kernel(const float* __restrict__ W,
                                                  const float* __restrict__ dec)
{
    const int bid = blockIdx.x;
    const int tid = threadIdx.x;
    if (bid < HH) {
        if (tid < K3 / 4) {
            int k = tid * 4;
            float4 f = *(const float4*)&W[bid * (4 * HH) + k];
            *(unsigned long long*)&g_whi[bid * K3 + k] = cvt4h(f);
        }
    } else {
        __shared__ float4 sdec[HH / 4];
        int b = bid - HH, h = tid;
        if (h < HH / 4) sdec[h] = *(const float4*)&dec[b * HH + h * 4];
        __syncthreads();
        const float4* w4 = (const float4*)(W + h * (4 * HH) + 3 * HH);
        float s0 = 0.f, s1 = 0.f, s2 = 0.f, s3 = 0.f;
#pragma unroll 8
        for (int i = 0; i < 32; i++) {
            float4 wv = w4[i];
            float4 dv = sdec[i];
            s0 += wv.x * dv.x; s1 += wv.y * dv.y;
            s2 += wv.z * dv.z; s3 += wv.w * dv.w;
        }
        g_dvec[b * HH + h] = (s0 + s1) + (s2 + s3);
    }
}

// ---------------------------------------------------------------------------
// Kernel B: fp16 HMMA GEMM, A via 3-slot cp.async, B via LDG-reg prefetch,
//           1 barrier/chunk, 3 CTAs/SM; fused tanh/v epilogue + softmax
// ---------------------------------------------------------------------------
__global__ void __launch_bounds__(256, 3)
score_kernel(const float* __restrict__ adj,
             const float* __restrict__ sta,
             const float* __restrict__ dyn,
             const float* __restrict__ v,
             float* __restrict__ out)
{
    extern __shared__ __align__(16) char smem[];
    __half* As   = (__half*)(smem + SO_A);
    __half* Bs_h = (__half*)(smem + SO_BS);
    float*  red  = (float*)(smem + SO_RED);
    float*  smx  = (float*)(smem + SO_SMX);

    const int tid  = threadIdx.x;
    const int lane = tid & 31;
    const int wrp  = tid >> 5;
    const int wm   = wrp >> 1;       // 0..3 (h quarter)
    const int wn   = wrp & 1;        // 0..1 (n half)
    const int b  = blockIdx.y;
    const int n0 = blockIdx.x * NT;

    const float* srcs[3] = {
        adj + (size_t)b * HH * NNODE,
        sta + (size_t)b * HH * NNODE,
        dyn + (size_t)b * HH * NNODE };

    const uint32_t uA = smem_u32(As);
    // A stage: cp.async chunk c into slot c%3; one commit group per call
    auto stage_A = [&](int c) {
        const int k0 = c * KC;
        const int sl = c % 3;
#pragma unroll
        for (int i = 0; i < 4; i++) {
            int idx = tid + i * 256;
            int row = idx >> 3, q = idx & 7;
            uint32_t doff = (uint32_t)((sl * AS1 + row * APAD + q * 8) * 2);
            CP16(uA + doff, &g_whi[row * K3 + k0 + q * 8]);
        }
        CP_COMMIT();
    };
    // B load: chunk c -> 4 float4 in registers (predicated, zero OOB)
    const int bq    = tid & 15;            // float4 col within row
    const int bkrow = tid >> 4;            // base k-row (stride 16)
    const bool binb = (n0 + bq * 4) < NNODE;
    auto ldB = [&](int c, float4* pre) {
        const int k0 = c * KC;
#pragma unroll
        for (int i = 0; i < 4; i++) {
            int kg = k0 + bkrow + i * 16;
            const float* src = srcs[kg >> 7] + (size_t)(kg & 127) * NNODE + n0 + bq * 4;
            pre[i] = binb ? *(const float4*)src : make_float4(0.f, 0.f, 0.f, 0.f);
        }
    };
    // B store: convert regs -> Bs slot s
    auto stB = [&](int s, const float4* pre) {
#pragma unroll
        for (int i = 0; i < 4; i++) {
            int krow = bkrow + i * 16;
            *(unsigned long long*)&Bs_h[s * BS1 + krow * BPAD + bq * 4] = cvt4h(pre[i]);
        }
    };

    float acc[2][4][4];
#pragma unroll
    for (int mt = 0; mt < 2; mt++)
#pragma unroll
        for (int nt = 0; nt < 4; nt++)
#pragma unroll
            for (int c = 0; c < 4; c++) acc[mt][nt][c] = 0.f;

    const uint32_t bsU = smem_u32(Bs_h);
    const int aRow = wm * 32 + (lane & 15);        // + mt*16
    const int aCol = (lane >> 4) * 8;              // + ks*16
    const int bRow = (lane & 15);                  // + ks*16
    const int bCol = wn * 32 + (lane >> 4) * 8;    // + ntg*16

    // ---- prologue: A chunks 0,1 in flight; B chunk 0 in regs
    stage_A(0);
    stage_A(1);
    float4 bpre[4];
    ldB(0, bpre);

    for (int it = 0; it < NCH; it++) {
        const int s = it & 1;
        stB(s, bpre);                         // convert+store chunk it
        if (it + 1 < NCH) ldB(it + 1, bpre);  // prefetch next into regs
        if (it + 1 < NCH) { CP_WAIT(1); }     // A chunk it arrived
        else              { CP_WAIT(0); }
        __syncthreads();                      // Bs[s] + As[it%3] visible; prev MMA done
        if (it + 2 < NCH) stage_A(it + 2);    // safe: slot (it+2)%3 not in use

        const uint32_t aOffS = (uint32_t)((it % 3) * AS1 * 2);
#pragma unroll
        for (int ks = 0; ks < 4; ks++) {
            uint32_t ah[2][4];
#pragma unroll
            for (int mt = 0; mt < 2; mt++) {
                uint32_t off = aOffS + (uint32_t)(((aRow + mt * 16) * APAD + ks * 16 + aCol) * 2);
                ldsm_x4(ah[mt][0], ah[mt][1], ah[mt][2], ah[mt][3], uA + off);
            }
            uint32_t bh[8];
#pragma unroll
            for (int ntg = 0; ntg < 2; ntg++) {
                uint32_t off = (uint32_t)((s * BS1 + (ks * 16 + bRow) * BPAD + bCol + ntg * 16) * 2);
                ldsm_x4_t(bh[ntg*4+0], bh[ntg*4+1], bh[ntg*4+2], bh[ntg*4+3], bsU + off);
            }
#pragma unroll
            for (int mt = 0; mt < 2; mt++)
#pragma unroll
                for (int nt = 0; nt < 4; nt++)
                    mma16816(acc[mt][nt], ah[mt], bh[nt*2+0], bh[nt*2+1]);
        }
    }

    // ---- epilogue: tanh(acc + d) * v, reduce over h -> logits
    const int g = lane >> 2, t = lane & 3;
    const float* dp = g_dvec + b * HH;
    float d0[2], d1[2], v0[2], v1[2];
#pragma unroll
    for (int mt = 0; mt < 2; mt++) {
        int h0 = wm * 32 + mt * 16 + g;
        d0[mt] = dp[h0];     d1[mt] = dp[h0 + 8];
        v0[mt] = v[h0];      v1[mt] = v[h0 + 8];
    }
    float p[4][2];
#pragma unroll
    for (int nt = 0; nt < 4; nt++)
#pragma unroll
        for (int c = 0; c < 2; c++) {
            float sacc = 0.f;
#pragma unroll
            for (int mt = 0; mt < 2; mt++)
                sacc += v0[mt] * tanh_fast(acc[mt][nt][c]     + d0[mt])
                      + v1[mt] * tanh_fast(acc[mt][nt][c + 2] + d1[mt]);
            p[nt][c] = sacc;
        }
#pragma unroll
    for (int m = 4; m <= 16; m <<= 1)
#pragma unroll
        for (int nt = 0; nt < 4; nt++)
#pragma unroll
            for (int c = 0; c < 2; c++)
                p[nt][c] += __shfl_xor_sync(0xFFFFFFFFu, p[nt][c], m);
    if (g == 0) {
#pragma unroll
        for (int nt = 0; nt < 4; nt++)
#pragma unroll
            for (int c = 0; c < 2; c++)
                red[wm * NT + wn * 32 + nt * 8 + t * 2 + c] = p[nt][c];
    }
    __syncthreads();
    if (tid < NT) {
        float sacc = red[0*NT+tid] + red[1*NT+tid] + red[2*NT+tid] + red[3*NT+tid];
        int n = n0 + tid;
        if (n < NNODE) g_attn[b * NPAD + n] = sacc;
    }

    // ---- fused softmax: last CTA of batch b does the row softmax
    __shared__ int is_last;
    __syncthreads();              // all logit writes issued
    __threadfence();              // order writes before the count
    if (tid == 0) is_last = (atomicAdd(&g_cnt[b], 1) == NTILES - 1);
    __syncthreads();
    if (is_last) {
        const float* row = &g_attn[b * NPAD];
        float m = -INFINITY;
        for (int n = tid; n < NNODE; n += 256) m = fmaxf(m, row[n]);
        smx[tid] = m;  __syncthreads();
        for (int sred = 128; sred > 0; sred >>= 1) {
            if (tid < sred) smx[tid] = fmaxf(smx[tid], smx[tid + sred]);
            __syncthreads();
        }
        m = smx[0];  __syncthreads();

        float sum = 0.f;
        for (int n = tid; n < NNODE; n += 256) sum += __expf(row[n] - m);
        smx[tid] = sum;  __syncthreads();
        for (int sred = 128; sred > 0; sred >>= 1) {
            if (tid < sred) smx[tid] += smx[tid + sred];
            __syncthreads();
        }
        float inv = 1.f / smx[0];

        for (int n = tid; n < NNODE; n += 256)
            out[b * NNODE + n] = __expf(row[n] - m) * inv;

        __syncthreads();
        if (tid == 0) g_cnt[b] = 0;   // reset for next graph replay
    }
}

// ---------------------------------------------------------------------------
extern "C" void kernel_launch(void* const* d_in, const int* in_sizes, int n_in,
                              void* d_out, int out_size)
{
    const float* adj = (const float*)d_in[0];
    const float* sta = (const float*)d_in[1];
    const float* dyn = (const float*)d_in[2];
    const float* dec = (const float*)d_in[3];
    const float* v   = (const float*)d_in[4];
    const float* W   = (const float*)d_in[5];
    float* out = (float*)d_out;

    cudaFuncSetAttribute(score_kernel,
                         cudaFuncAttributeMaxDynamicSharedMemorySize, SMEM_SZ);

    prep_kernel<<<HH + BB, HH>>>(W, dec);        // 384 CTAs: wpack + dvec
    dim3 grid(NTILES, BB);                       // (16, 256)
    score_kernel<<<grid, 256, SMEM_SZ>>>(adj, sta, dyn, v, out);
}

// round 15
// speedup vs baseline: 1.2442x; 1.2442x over previous
#include <cuda_runtime.h>
#include <cuda_fp16.h>
#include <cstdint>
#include <cstddef>
#include <math.h>

#define BB    256
#define HH    128
#define NNODE 1000
#define NPAD  1024
#define K3    384
#define KC    64          // k per chunk (4 x k16 steps)
#define NCH   (K3 / KC)   // 6
#define NT    64          // n per CTA
#define NTILES (NPAD / NT) // 16 CTAs per batch
#define APAD  72          // As row stride (fp16)
#define BPAD  72          // Bs row stride (fp16)
#define BFW   68          // Bf fp32 staging row stride (floats)

#define AS1   (HH * APAD)     // 9216 halfs (single A buffer)
#define BF1   (KC * BFW)      // 4352 floats per Bf buffer
#define BS1   (KC * BPAD)     // 4608 halfs (single Bs buffer)

// ---------------- scratch (__device__ globals) -----------------------------
__device__ float g_dvec[BB * HH];
__device__ float g_attn[BB * NPAD];
__device__ __half g_whi[HH * K3];
__device__ int   g_cnt[BB];              // zero-init; reset after use (graph-safe)

// ---------------- helpers --------------------------------------------------
__device__ __forceinline__ uint32_t smem_u32(const void* p) {
    uint32_t a;
    asm("{ .reg .u64 t; cvta.to.shared.u64 t, %1; cvt.u32.u64 %0, t; }" : "=r"(a) : "l"(p));
    return a;
}
#define CP16(dst, src) \
    asm volatile("cp.async.cg.shared.global [%0], [%1], 16;" :: "r"(dst), "l"(src))
#define CP16Z(dst, src, nb) \
    asm volatile("cp.async.cg.shared.global [%0], [%1], 16, %2;" :: "r"(dst), "l"(src), "r"(nb))
#define CP_COMMIT() asm volatile("cp.async.commit_group;")
#define CP_WAIT(n)  asm volatile("cp.async.wait_group %0;" :: "n"(n))

__device__ __forceinline__ void ldsm_x4(uint32_t& r0, uint32_t& r1,
                                        uint32_t& r2, uint32_t& r3, uint32_t a) {
    asm volatile("ldmatrix.sync.aligned.m8n8.x4.shared.b16 {%0,%1,%2,%3}, [%4];"
                 : "=r"(r0), "=r"(r1), "=r"(r2), "=r"(r3) : "r"(a));
}
__device__ __forceinline__ void ldsm_x4_t(uint32_t& r0, uint32_t& r1,
                                          uint32_t& r2, uint32_t& r3, uint32_t a) {
    asm volatile("ldmatrix.sync.aligned.m8n8.x4.trans.shared.b16 {%0,%1,%2,%3}, [%4];"
                 : "=r"(r0), "=r"(r1), "=r"(r2), "=r"(r3) : "r"(a));
}
__device__ __forceinline__ void mma16816(float* c, const uint32_t* a,
                                         uint32_t b0, uint32_t b1) {
    asm volatile("mma.sync.aligned.m16n8k16.row.col.f32.f16.f16.f32 "
                 "{%0,%1,%2,%3}, {%4,%5,%6,%7}, {%8,%9}, {%0,%1,%2,%3};"
                 : "+f"(c[0]), "+f"(c[1]), "+f"(c[2]), "+f"(c[3])
                 : "r"(a[0]), "r"(a[1]), "r"(a[2]), "r"(a[3]), "r"(b0), "r"(b1));
}
// fp32x4 -> packed fp16x4
__device__ __forceinline__ unsigned long long cvt4h(float4 f) {
    __half2 p0 = __floats2half2_rn(f.x, f.y);
    __half2 p1 = __floats2half2_rn(f.z, f.w);
    union { __half2 h[2]; unsigned long long u; } r;
    r.h[0] = p0; r.h[1] = p1;
    return r.u;
}
__device__ __forceinline__ float tanh_fast(float x) {
    float t = __expf(2.f * x);
    return 1.f - __fdividef(2.f, t + 1.f);
}

// SMEM layout (bytes)
#define SO_A    0                              // 1 x AS1 fp16 = 18432
#define SO_BF   (SO_A + AS1 * 2)               // 18432: 2 x BF1 fp32 = 34816
#define SO_BSH  (SO_BF + 2 * BF1 * 4)          // 53248: 1 x BS1 fp16 = 9216
#define SO_RED  (SO_BSH + BS1 * 2)             // 62464: 4*64 fp32 = 1024
#define SO_SMX  (SO_RED + 4 * NT * 4)          // 63488: 256 fp32 = 1024
#define SMEM_SZ (SO_SMX + 256 * 4)             // 64512  (x3 CTA = 193.5KB)

// ---------------------------------------------------------------------------
// Prep kernel: CTAs [0,128) pack W -> fp16; CTAs [128,384) dvec
// ---------------------------------------------------------------------------
__global__ void __launch_bounds__(HH) prep_kernel(const float* __restrict__ W,
                                                  const float* __restrict__ dec)
{
    const int bid = blockIdx.x;
    const int tid = threadIdx.x;
    if (bid < HH) {
        if (tid < K3 / 4) {
            int k = tid * 4;
            float4 f = *(const float4*)&W[bid * (4 * HH) + k];
            *(unsigned long long*)&g_whi[bid * K3 + k] = cvt4h(f);
        }
    } else {
        __shared__ float4 sdec[HH / 4];
        int b = bid - HH, h = tid;
        if (h < HH / 4) sdec[h] = *(const float4*)&dec[b * HH + h * 4];
        __syncthreads();
        const float4* w4 = (const float4*)(W + h * (4 * HH) + 3 * HH);
        float s0 = 0.f, s1 = 0.f, s2 = 0.f, s3 = 0.f;
#pragma unroll 8
        for (int i = 0; i < 32; i++) {
            float4 wv = w4[i];
            float4 dv = sdec[i];
            s0 += wv.x * dv.x; s1 += wv.y * dv.y;
            s2 += wv.z * dv.z; s3 += wv.w * dv.w;
        }
        g_dvec[b * HH + h] = (s0 + s1) + (s2 + s3);
    }
}

// ---------------------------------------------------------------------------
// Kernel B: fp16 HMMA GEMM; A single-buffer cp.async (L2-hot), B double-buffer
//           cp.async prefetch; 3 CTAs/SM; fused tanh/v epilogue + softmax
// ---------------------------------------------------------------------------
__global__ void __launch_bounds__(256, 3)
score_kernel(const float* __restrict__ adj,
             const float* __restrict__ sta,
             const float* __restrict__ dyn,
             const float* __restrict__ v,
             float* __restrict__ out)
{
    extern __shared__ __align__(16) char smem[];
    __half* As   = (__half*)(smem + SO_A);
    float*  Bf   = (float*)(smem + SO_BF);
    __half* Bs_h = (__half*)(smem + SO_BSH);
    float*  red  = (float*)(smem + SO_RED);
    float*  smx  = (float*)(smem + SO_SMX);

    const int tid  = threadIdx.x;
    const int lane = tid & 31;
    const int wrp  = tid >> 5;
    const int wm   = wrp >> 1;       // 0..3 (h quarter)
    const int wn   = wrp & 1;        // 0..1 (n half)
    const int b  = blockIdx.y;
    const int n0 = blockIdx.x * NT;

    const float* srcs[3] = {
        adj + (size_t)b * HH * NNODE,
        sta + (size_t)b * HH * NNODE,
        dyn + (size_t)b * HH * NNODE };

    const uint32_t uA  = smem_u32(As);
    const uint32_t uBf = smem_u32(Bf);
    // A: chunk c -> single As buffer (own commit group)
    auto stage_A = [&](int c) {
        const int k0 = c * KC;
#pragma unroll
        for (int i = 0; i < 4; i++) {
            int idx = tid + i * 256;
            int row = idx >> 3, q = idx & 7;
            uint32_t doff = (uint32_t)((row * APAD + q * 8) * 2);
            CP16(uA + doff, &g_whi[row * K3 + k0 + q * 8]);
        }
        CP_COMMIT();
    };
    // B: chunk c -> Bf slot s (own commit group), zero-fill OOB
    auto stage_B = [&](int c, int s) {
        const int k0 = c * KC;
#pragma unroll
        for (int i = 0; i < 4; i++) {
            int idx = tid + i * 256;
            int krow = idx >> 4, q = idx & 15;
            int kg = k0 + krow;
            const float* src = srcs[kg >> 7] + (size_t)(kg & 127) * NNODE + n0 + q * 4;
            uint32_t doff = (uint32_t)((s * BF1 + krow * BFW + q * 4) * 4);
            uint32_t nb = (n0 + q * 4 < NNODE) ? 16u : 0u;
            CP16Z(uBf + doff, src, nb);
        }
        CP_COMMIT();
    };

    float acc[2][4][4];
#pragma unroll
    for (int mt = 0; mt < 2; mt++)
#pragma unroll
        for (int nt = 0; nt < 4; nt++)
#pragma unroll
            for (int c = 0; c < 4; c++) acc[mt][nt][c] = 0.f;

    const uint32_t bsU = smem_u32(Bs_h);
    const int aRow = wm * 32 + (lane & 15);        // + mt*16
    const int aCol = (lane >> 4) * 8;              // + ks*16
    const int bRow = (lane & 15);                  // + ks*16
    const int bCol = wn * 32 + (lane >> 4) * 8;    // + ntg*16

    stage_B(0, 0);                                  // prologue: B chunk 0 in flight

    for (int it = 0; it < NCH; it++) {
        const int s = it & 1;
        __syncthreads();                 // prev compute reads (As, Bs) done
        stage_A(it);                     // group: A(it)
        if (it + 1 < NCH) { stage_B(it + 1, s ^ 1); CP_WAIT(1); }  // B(it),A(it) done
        else              { CP_WAIT(0); }
        __syncthreads();                 // As + Bf[s] visible

        // ---- convert B fp32 -> fp16 (64 rows x 16 float4)
#pragma unroll
        for (int i = 0; i < 4; i++) {
            int idx = tid + i * 256;
            int krow = idx >> 4, q = idx & 15;
            float4 f = *(float4*)&Bf[s * BF1 + krow * BFW + q * 4];
            *(unsigned long long*)&Bs_h[krow * BPAD + q * 4] = cvt4h(f);
        }
        __syncthreads();                 // Bs ready

#pragma unroll
        for (int ks = 0; ks < 4; ks++) {
            uint32_t ah[2][4];
#pragma unroll
            for (int mt = 0; mt < 2; mt++) {
                uint32_t off = (uint32_t)(((aRow + mt * 16) * APAD + ks * 16 + aCol) * 2);
                ldsm_x4(ah[mt][0], ah[mt][1], ah[mt][2], ah[mt][3], uA + off);
            }
            uint32_t bh[8];
#pragma unroll
            for (int ntg = 0; ntg < 2; ntg++) {
                uint32_t off = (uint32_t)(((ks * 16 + bRow) * BPAD + bCol + ntg * 16) * 2);
                ldsm_x4_t(bh[ntg*4+0], bh[ntg*4+1], bh[ntg*4+2], bh[ntg*4+3], bsU + off);
            }
#pragma unroll
            for (int mt = 0; mt < 2; mt++)
#pragma unroll
                for (int nt = 0; nt < 4; nt++)
                    mma16816(acc[mt][nt], ah[mt], bh[nt*2+0], bh[nt*2+1]);
        }
    }

    // ---- epilogue: tanh(acc + d) * v, reduce over h -> logits
    const int g = lane >> 2, t = lane & 3;
    const float* dp = g_dvec + b * HH;
    float d0[2], d1[2], v0[2], v1[2];
#pragma unroll
    for (int mt = 0; mt < 2; mt++) {
        int h0 = wm * 32 + mt * 16 + g;
        d0[mt] = dp[h0];     d1[mt] = dp[h0 + 8];
        v0[mt] = v[h0];      v1[mt] = v[h0 + 8];
    }
    float p[4][2];
#pragma unroll
    for (int nt = 0; nt < 4; nt++)
#pragma unroll
        for (int c = 0; c < 2; c++) {
            float sacc = 0.f;
#pragma unroll
            for (int mt = 0; mt < 2; mt++)
                sacc += v0[mt] * tanh_fast(acc[mt][nt][c]     + d0[mt])
                      + v1[mt] * tanh_fast(acc[mt][nt][c + 2] + d1[mt]);
            p[nt][c] = sacc;
        }
#pragma unroll
    for (int m = 4; m <= 16; m <<= 1)
#pragma unroll
        for (int nt = 0; nt < 4; nt++)
#pragma unroll
            for (int c = 0; c < 2; c++)
                p[nt][c] += __shfl_xor_sync(0xFFFFFFFFu, p[nt][c], m);
    if (g == 0) {
#pragma unroll
        for (int nt = 0; nt < 4; nt++)
#pragma unroll
            for (int c = 0; c < 2; c++)
                red[wm * NT + wn * 32 + nt * 8 + t * 2 + c] = p[nt][c];
    }
    __syncthreads();
    if (tid < NT) {
        float sacc = red[0*NT+tid] + red[1*NT+tid] + red[2*NT+tid] + red[3*NT+tid];
        int n = n0 + tid;
        if (n < NNODE) g_attn[b * NPAD + n] = sacc;
    }

    // ---- fused softmax: last CTA of batch b does the row softmax
    __shared__ int is_last;
    __syncthreads();              // all logit writes issued
    __threadfence();              // order writes before the count
    if (tid == 0) is_last = (atomicAdd(&g_cnt[b], 1) == NTILES - 1);
    __syncthreads();
    if (is_last) {
        const float* row = &g_attn[b * NPAD];
        float m = -INFINITY;
        for (int n = tid; n < NNODE; n += 256) m = fmaxf(m, row[n]);
        smx[tid] = m;  __syncthreads();
        for (int sred = 128; sred > 0; sred >>= 1) {
            if (tid < sred) smx[tid] = fmaxf(smx[tid], smx[tid + sred]);
            __syncthreads();
        }
        m = smx[0];  __syncthreads();

        float sum = 0.f;
        for (int n = tid; n < NNODE; n += 256) sum += __expf(row[n] - m);
        smx[tid] = sum;  __syncthreads();
        for (int sred = 128; sred > 0; sred >>= 1) {
            if (tid < sred) smx[tid] += smx[tid + sred];
            __syncthreads();
        }
        float inv = 1.f / smx[0];

        for (int n = tid; n < NNODE; n += 256)
            out[b * NNODE + n] = __expf(row[n] - m) * inv;

        __syncthreads();
        if (tid == 0) g_cnt[b] = 0;   // reset for next graph replay
    }
}

// ---------------------------------------------------------------------------
extern "C" void kernel_launch(void* const* d_in, const int* in_sizes, int n_in,
                              void* d_out, int out_size)
{
    const float* adj = (const float*)d_in[0];
    const float* sta = (const float*)d_in[1];
    const float* dyn = (const float*)d_in[2];
    const float* dec = (const float*)d_in[3];
    const float* v   = (const float*)d_in[4];
    const float* W   = (const float*)d_in[5];
    float* out = (float*)d_out;

    cudaFuncSetAttribute(score_kernel,
                         cudaFuncAttributeMaxDynamicSharedMemorySize, SMEM_SZ);

    prep_kernel<<<HH + BB, HH>>>(W, dec);        // 384 CTAs: wpack + dvec
    dim3 grid(NTILES, BB);                       // (16, 256)
    score_kernel<<<grid, 256, SMEM_SZ>>>(adj, sta, dyn, v, out);
}

// round 16
// speedup vs baseline: 1.3528x; 1.0873x over previous
#include <cuda_runtime.h>
#include <cuda_fp16.h>
#include <cstdint>
#include <cstddef>
#include <math.h>

#define BB    256
#define HH    128
#define NNODE 1000
#define NPAD  1024
#define K3    384
#define KC    64          // k per chunk (4 x k16 steps)
#define NCH   (K3 / KC)   // 6
#define NKBLK (K3 / 16)   // 24 k16 blocks
#define NHBLK (HH / 16)   // 8 h16 blocks
#define NT    64          // n per CTA
#define NTILES (NPAD / NT) // 16 CTAs per batch
#define BPAD  72          // Bs row stride (fp16)
#define BFW   68          // Bf fp32 staging row stride (floats)

#define BF1   (KC * BFW)      // 4352 floats per Bf buffer
#define BS1   (KC * BPAD)     // 4608 halfs (single Bs buffer)

// ---------------- scratch (__device__ globals) -----------------------------
__device__ float g_dvec[BB * HH];
__device__ float g_attn[BB * NPAD];
__device__ uint4 g_wfrag[NKBLK * NHBLK * 32];   // W in mma-frag order, 96KB
__device__ int   g_cnt[BB];                     // zero-init; reset after use

// ---------------- helpers --------------------------------------------------
__device__ __forceinline__ uint32_t smem_u32(const void* p) {
    uint32_t a;
    asm("{ .reg .u64 t; cvta.to.shared.u64 t, %1; cvt.u32.u64 %0, t; }" : "=r"(a) : "l"(p));
    return a;
}
#define CP16Z(dst, src, nb) \
    asm volatile("cp.async.cg.shared.global [%0], [%1], 16, %2;" :: "r"(dst), "l"(src), "r"(nb))
#define CP_COMMIT() asm volatile("cp.async.commit_group;")
#define CP_WAIT(n)  asm volatile("cp.async.wait_group %0;" :: "n"(n))

__device__ __forceinline__ void ldsm_x4_t(uint32_t& r0, uint32_t& r1,
                                          uint32_t& r2, uint32_t& r3, uint32_t a) {
    asm volatile("ldmatrix.sync.aligned.m8n8.x4.trans.shared.b16 {%0,%1,%2,%3}, [%4];"
                 : "=r"(r0), "=r"(r1), "=r"(r2), "=r"(r3) : "r"(a));
}
__device__ __forceinline__ void mma16816(float* c, const uint32_t* a,
                                         uint32_t b0, uint32_t b1) {
    asm volatile("mma.sync.aligned.m16n8k16.row.col.f32.f16.f16.f32 "
                 "{%0,%1,%2,%3}, {%4,%5,%6,%7}, {%8,%9}, {%0,%1,%2,%3};"
                 : "+f"(c[0]), "+f"(c[1]), "+f"(c[2]), "+f"(c[3])
                 : "r"(a[0]), "r"(a[1]), "r"(a[2]), "r"(a[3]), "r"(b0), "r"(b1));
}
// fp32x4 -> packed fp16x4
__device__ __forceinline__ unsigned long long cvt4h(float4 f) {
    __half2 p0 = __floats2half2_rn(f.x, f.y);
    __half2 p1 = __floats2half2_rn(f.z, f.w);
    union { __half2 h[2]; unsigned long long u; } r;
    r.h[0] = p0; r.h[1] = p1;
    return r.u;
}
__device__ __forceinline__ uint32_t pack2h(float a, float b) {
    __half2 p = __floats2half2_rn(a, b);
    return *(uint32_t*)&p;
}
__device__ __forceinline__ float tanh_fast(float x) {
    float t = __expf(2.f * x);
    return 1.f - __fdividef(2.f, t + 1.f);
}

// SMEM layout (bytes)
#define SO_BF   0                              // 2 x BF1 fp32 = 34816
#define SO_BSH  (SO_BF + 2 * BF1 * 4)          // 34816: BS1 fp16 = 9216
#define SO_RED  (SO_BSH + BS1 * 2)             // 44032: 4*64 fp32 = 1024
#define SO_SMX  (SO_RED + 4 * NT * 4)          // 45056: 256 fp32 = 1024
#define SMEM_SZ (SO_SMX + 256 * 4)             // 46080  (x3 CTA = 138KB)

// ---------------------------------------------------------------------------
// Prep kernel:
//   CTAs [0, 192): W -> mma-fragment layout (bid = kblk*8 + hblk, 32 lanes)
//   CTAs [192, 192+256): dvec
// ---------------------------------------------------------------------------
__global__ void __launch_bounds__(HH) prep_kernel(const float* __restrict__ W,
                                                  const float* __restrict__ dec)
{
    const int bid = blockIdx.x;
    const int tid = threadIdx.x;
    if (bid < NKBLK * NHBLK) {
        if (tid < 32) {
            const int kblk = bid >> 3, hblk = bid & 7;
            const int g = tid >> 2, t = tid & 3;
            const int h0 = hblk * 16 + g, h1 = h0 + 8;
            const int k0 = kblk * 16 + t * 2, k1 = k0 + 8;
            const float* W0 = W + h0 * (4 * HH);
            const float* W1 = W + h1 * (4 * HH);
            uint4 f;
            f.x = pack2h(W0[k0], W0[k0 + 1]);     // a0: (g,   2t)
            f.y = pack2h(W1[k0], W1[k0 + 1]);     // a1: (g+8, 2t)
            f.z = pack2h(W0[k1], W0[k1 + 1]);     // a2: (g,   2t+8)
            f.w = pack2h(W1[k1], W1[k1 + 1]);     // a3: (g+8, 2t+8)
            g_wfrag[(size_t)bid * 32 + tid] = f;
        }
    } else {
        __shared__ float4 sdec[HH / 4];
        int b = bid - NKBLK * NHBLK, h = tid;
        if (h < HH / 4) sdec[h] = *(const float4*)&dec[b * HH + h * 4];
        __syncthreads();
        const float4* w4 = (const float4*)(W + h * (4 * HH) + 3 * HH);
        float s0 = 0.f, s1 = 0.f, s2 = 0.f, s3 = 0.f;
#pragma unroll 8
        for (int i = 0; i < 32; i++) {
            float4 wv = w4[i];
            float4 dv = sdec[i];
            s0 += wv.x * dv.x; s1 += wv.y * dv.y;
            s2 += wv.z * dv.z; s3 += wv.w * dv.w;
        }
        g_dvec[b * HH + h] = (s0 + s1) + (s2 + s3);
    }
}

// ---------------------------------------------------------------------------
// Kernel B: fp16 HMMA GEMM; A via coalesced LDG of prepacked fragments
//           (no A smem traffic), B double-buffered cp.async + convert;
//           3 CTAs/SM; fused tanh/v epilogue + softmax
// ---------------------------------------------------------------------------
__global__ void __launch_bounds__(256, 3)
score_kernel(const float* __restrict__ adj,
             const float* __restrict__ sta,
             const float* __restrict__ dyn,
             const float* __restrict__ v,
             float* __restrict__ out)
{
    extern __shared__ __align__(16) char smem[];
    float*  Bf   = (float*)(smem + SO_BF);
    __half* Bs_h = (__half*)(smem + SO_BSH);
    float*  red  = (float*)(smem + SO_RED);
    float*  smx  = (float*)(smem + SO_SMX);

    const int tid  = threadIdx.x;
    const int lane = tid & 31;
    const int wrp  = tid >> 5;
    const int wm   = wrp >> 1;       // 0..3 (h quarter)
    const int wn   = wrp & 1;        // 0..1 (n half)
    const int b  = blockIdx.y;
    const int n0 = blockIdx.x * NT;

    const float* srcs[3] = {
        adj + (size_t)b * HH * NNODE,
        sta + (size_t)b * HH * NNODE,
        dyn + (size_t)b * HH * NNODE };

    const uint32_t uBf = smem_u32(Bf);
    // B: chunk c -> Bf slot s (own commit group), zero-fill OOB
    auto stage_B = [&](int c, int s) {
        const int k0 = c * KC;
#pragma unroll
        for (int i = 0; i < 4; i++) {
            int idx = tid + i * 256;
            int krow = idx >> 4, q = idx & 15;
            int kg = k0 + krow;
            const float* src = srcs[kg >> 7] + (size_t)(kg & 127) * NNODE + n0 + q * 4;
            uint32_t doff = (uint32_t)((s * BF1 + krow * BFW + q * 4) * 4);
            uint32_t nb = (n0 + q * 4 < NNODE) ? 16u : 0u;
            CP16Z(uBf + doff, src, nb);
        }
        CP_COMMIT();
    };

    float acc[2][4][4];
#pragma unroll
    for (int mt = 0; mt < 2; mt++)
#pragma unroll
        for (int nt = 0; nt < 4; nt++)
#pragma unroll
            for (int c = 0; c < 4; c++) acc[mt][nt][c] = 0.f;

    const uint32_t bsU = smem_u32(Bs_h);
    const int bRow = (lane & 15);                  // + ks*16
    const int bCol = wn * 32 + (lane >> 4) * 8;    // + ntg*16
    // A fragment base: lane's 16B within (kblk, hblk) frag
    const uint4* wf = g_wfrag + lane;

    stage_B(0, 0);                                  // prologue

    for (int it = 0; it < NCH; it++) {
        const int s = it & 1;
        __syncthreads();                 // prev Bs/Bf reads done
        if (it + 1 < NCH) { stage_B(it + 1, s ^ 1); CP_WAIT(1); }
        else              { CP_WAIT(0); }
        __syncthreads();                 // Bf[s] visible

        // ---- convert B fp32 -> fp16 (64 rows x 16 float4)
#pragma unroll
        for (int i = 0; i < 4; i++) {
            int idx = tid + i * 256;
            int krow = idx >> 4, q = idx & 15;
            float4 f = *(float4*)&Bf[s * BF1 + krow * BFW + q * 4];
            *(unsigned long long*)&Bs_h[krow * BPAD + q * 4] = cvt4h(f);
        }
        __syncthreads();                 // Bs ready

#pragma unroll
        for (int ks = 0; ks < 4; ks++) {
            const int kblk = it * 4 + ks;
            // A fragments via coalesced LDG.128 (L1/L2-hot prepacked W)
            uint4 a0 = wf[((size_t)kblk * 8 + (wm * 2 + 0)) * 32];
            uint4 a1 = wf[((size_t)kblk * 8 + (wm * 2 + 1)) * 32];
            uint32_t ah[2][4] = {{a0.x, a0.y, a0.z, a0.w}, {a1.x, a1.y, a1.z, a1.w}};
            uint32_t bh[8];
#pragma unroll
            for (int ntg = 0; ntg < 2; ntg++) {
                uint32_t off = (uint32_t)(((ks * 16 + bRow) * BPAD + bCol + ntg * 16) * 2);
                ldsm_x4_t(bh[ntg*4+0], bh[ntg*4+1], bh[ntg*4+2], bh[ntg*4+3], bsU + off);
            }
#pragma unroll
            for (int mt = 0; mt < 2; mt++)
#pragma unroll
                for (int nt = 0; nt < 4; nt++)
                    mma16816(acc[mt][nt], ah[mt], bh[nt*2+0], bh[nt*2+1]);
        }
    }

    // ---- epilogue: tanh(acc + d) * v, reduce over h -> logits
    const int g = lane >> 2, t = lane & 3;
    const float* dp = g_dvec + b * HH;
    float d0[2], d1[2], v0[2], v1[2];
#pragma unroll
    for (int mt = 0; mt < 2; mt++) {
        int h0 = wm * 32 + mt * 16 + g;
        d0[mt] = dp[h0];     d1[mt] = dp[h0 + 8];
        v0[mt] = v[h0];      v1[mt] = v[h0 + 8];
    }
    float p[4][2];
#pragma unroll
    for (int nt = 0; nt < 4; nt++)
#pragma unroll
        for (int c = 0; c < 2; c++) {
            float sacc = 0.f;
#pragma unroll
            for (int mt = 0; mt < 2; mt++)
                sacc += v0[mt] * tanh_fast(acc[mt][nt][c]     + d0[mt])
                      + v1[mt] * tanh_fast(acc[mt][nt][c + 2] + d1[mt]);
            p[nt][c] = sacc;
        }
#pragma unroll
    for (int m = 4; m <= 16; m <<= 1)
#pragma unroll
        for (int nt = 0; nt < 4; nt++)
#pragma unroll
            for (int c = 0; c < 2; c++)
                p[nt][c] += __shfl_xor_sync(0xFFFFFFFFu, p[nt][c], m);
    if (g == 0) {
#pragma unroll
        for (int nt = 0; nt < 4; nt++)
#pragma unroll
            for (int c = 0; c < 2; c++)
                red[wm * NT + wn * 32 + nt * 8 + t * 2 + c] = p[nt][c];
    }
    __syncthreads();
    if (tid < NT) {
        float sacc = red[0*NT+tid] + red[1*NT+tid] + red[2*NT+tid] + red[3*NT+tid];
        int n = n0 + tid;
        if (n < NNODE) g_attn[b * NPAD + n] = sacc;
    }

    // ---- fused softmax: last CTA of batch b does the row softmax
    __shared__ int is_last;
    __syncthreads();              // all logit writes issued
    __threadfence();              // order writes before the count
    if (tid == 0) is_last = (atomicAdd(&g_cnt[b], 1) == NTILES - 1);
    __syncthreads();
    if (is_last) {
        const float* row = &g_attn[b * NPAD];
        float m = -INFINITY;
        for (int n = tid; n < NNODE; n += 256) m = fmaxf(m, row[n]);
        smx[tid] = m;  __syncthreads();
        for (int sred = 128; sred > 0; sred >>= 1) {
            if (tid < sred) smx[tid] = fmaxf(smx[tid], smx[tid + sred]);
            __syncthreads();
        }
        m = smx[0];  __syncthreads();

        float sum = 0.f;
        for (int n = tid; n < NNODE; n += 256) sum += __expf(row[n] - m);
        smx[tid] = sum;  __syncthreads();
        for (int sred = 128; sred > 0; sred >>= 1) {
            if (tid < sred) smx[tid] += smx[tid + sred];
            __syncthreads();
        }
        float inv = 1.f / smx[0];

        for (int n = tid; n < NNODE; n += 256)
            out[b * NNODE + n] = __expf(row[n] - m) * inv;

        __syncthreads();
        if (tid == 0) g_cnt[b] = 0;   // reset for next graph replay
    }
}

// ---------------------------------------------------------------------------
extern "C" void kernel_launch(void* const* d_in, const int* in_sizes, int n_in,
                              void* d_out, int out_size)
{
    const float* adj = (const float*)d_in[0];
    const float* sta = (const float*)d_in[1];
    const float* dyn = (const float*)d_in[2];
    const float* dec = (const float*)d_in[3];
    const float* v   = (const float*)d_in[4];
    const float* W   = (const float*)d_in[5];
    float* out = (float*)d_out;

    cudaFuncSetAttribute(score_kernel,
                         cudaFuncAttributeMaxDynamicSharedMemorySize, SMEM_SZ);

    prep_kernel<<<NKBLK * NHBLK + BB, HH>>>(W, dec);  // 448 CTAs: wfrag + dvec
    dim3 grid(NTILES, BB);                            // (16, 256)
    score_kernel<<<grid, 256, SMEM_SZ>>>(adj, sta, dyn, v, out);
}

// round 17
// speedup vs baseline: 1.4727x; 1.0886x over previous
#include <cuda_runtime.h>
#include <cuda_fp16.h>
#include <cstdint>
#include <cstddef>
#include <math.h>

#define BB    256
#define HH    128
#define NNODE 1000
#define NPAD  1024
#define K3    384
#define KC    64          // k per chunk (4 x k16 steps)
#define NCH   (K3 / KC)   // 6
#define NKBLK (K3 / 16)   // 24 k16 blocks
#define NHBLK (HH / 16)   // 8 h16 blocks
#define NT    128         // n per CTA
#define NTILES (NPAD / NT) // 8 CTAs per batch
#define BPAD  136         // Bs row stride (fp16): 128 + 8 pad
#define BFW   132         // Bf fp32 staging row stride (floats)

#define BF1   (KC * BFW)      // 8448 floats per Bf buffer
#define BS1   (KC * BPAD)     // 8704 halfs (single Bs buffer)

// ---------------- scratch (__device__ globals) -----------------------------
__device__ float g_dvec[BB * HH];
__device__ float g_attn[BB * NPAD];
__device__ uint4 g_wfrag[NKBLK * NHBLK * 32];   // W in mma-frag order, 96KB
__device__ int   g_cnt[BB];                     // zero-init; reset after use

// ---------------- helpers --------------------------------------------------
__device__ __forceinline__ uint32_t smem_u32(const void* p) {
    uint32_t a;
    asm("{ .reg .u64 t; cvta.to.shared.u64 t, %1; cvt.u32.u64 %0, t; }" : "=r"(a) : "l"(p));
    return a;
}
#define CP16Z(dst, src, nb) \
    asm volatile("cp.async.cg.shared.global [%0], [%1], 16, %2;" :: "r"(dst), "l"(src), "r"(nb))
#define CP_COMMIT() asm volatile("cp.async.commit_group;")
#define CP_WAIT(n)  asm volatile("cp.async.wait_group %0;" :: "n"(n))

__device__ __forceinline__ void ldsm_x4_t(uint32_t& r0, uint32_t& r1,
                                          uint32_t& r2, uint32_t& r3, uint32_t a) {
    asm volatile("ldmatrix.sync.aligned.m8n8.x4.trans.shared.b16 {%0,%1,%2,%3}, [%4];"
                 : "=r"(r0), "=r"(r1), "=r"(r2), "=r"(r3) : "r"(a));
}
__device__ __forceinline__ void mma16816(float* c, const uint32_t* a,
                                         uint32_t b0, uint32_t b1) {
    asm volatile("mma.sync.aligned.m16n8k16.row.col.f32.f16.f16.f32 "
                 "{%0,%1,%2,%3}, {%4,%5,%6,%7}, {%8,%9}, {%0,%1,%2,%3};"
                 : "+f"(c[0]), "+f"(c[1]), "+f"(c[2]), "+f"(c[3])
                 : "r"(a[0]), "r"(a[1]), "r"(a[2]), "r"(a[3]), "r"(b0), "r"(b1));
}
// fp32x4 -> packed fp16x4
__device__ __forceinline__ unsigned long long cvt4h(float4 f) {
    __half2 p0 = __floats2half2_rn(f.x, f.y);
    __half2 p1 = __floats2half2_rn(f.z, f.w);
    union { __half2 h[2]; unsigned long long u; } r;
    r.h[0] = p0; r.h[1] = p1;
    return r.u;
}
__device__ __forceinline__ uint32_t pack2h(float a, float b) {
    __half2 p = __floats2half2_rn(a, b);
    return *(uint32_t*)&p;
}
__device__ __forceinline__ float tanh_fast(float x) {
    float t = __expf(2.f * x);
    return 1.f - __fdividef(2.f, t + 1.f);
}

// SMEM layout (bytes)
#define SO_BF   0                              // 2 x BF1 fp32 = 67584
#define SO_BSH  (SO_BF + 2 * BF1 * 4)          // 67584: BS1 fp16 = 17408
#define SO_RED  (SO_BSH + BS1 * 2)             // 84992: 4*128 fp32 = 2048
#define SO_SMX  (SO_RED + 4 * NT * 4)          // 87040: 256 fp32 = 1024
#define SMEM_SZ (SO_SMX + 256 * 4)             // 88064  (x2 CTA = 176KB)

// ---------------------------------------------------------------------------
// Prep kernel:
//   CTAs [0, 192): W -> mma-fragment layout (bid = kblk*8 + hblk, 32 lanes)
//   CTAs [192, 192+256): dvec
// ---------------------------------------------------------------------------
__global__ void __launch_bounds__(HH) prep_kernel(const float* __restrict__ W,
                                                  const float* __restrict__ dec)
{
    const int bid = blockIdx.x;
    const int tid = threadIdx.x;
    if (bid < NKBLK * NHBLK) {
        if (tid < 32) {
            const int kblk = bid >> 3, hblk = bid & 7;
            const int g = tid >> 2, t = tid & 3;
            const int h0 = hblk * 16 + g, h1 = h0 + 8;
            const int k0 = kblk * 16 + t * 2, k1 = k0 + 8;
            const float* W0 = W + h0 * (4 * HH);
            const float* W1 = W + h1 * (4 * HH);
            uint4 f;
            f.x = pack2h(W0[k0], W0[k0 + 1]);     // a0: (g,   2t)
            f.y = pack2h(W1[k0], W1[k0 + 1]);     // a1: (g+8, 2t)
            f.z = pack2h(W0[k1], W0[k1 + 1]);     // a2: (g,   2t+8)
            f.w = pack2h(W1[k1], W1[k1 + 1]);     // a3: (g+8, 2t+8)
            g_wfrag[(size_t)bid * 32 + tid] = f;
        }
    } else {
        __shared__ float4 sdec[HH / 4];
        int b = bid - NKBLK * NHBLK, h = tid;
        if (h < HH / 4) sdec[h] = *(const float4*)&dec[b * HH + h * 4];
        __syncthreads();
        const float4* w4 = (const float4*)(W + h * (4 * HH) + 3 * HH);
        float s0 = 0.f, s1 = 0.f, s2 = 0.f, s3 = 0.f;
#pragma unroll 8
        for (int i = 0; i < 32; i++) {
            float4 wv = w4[i];
            float4 dv = sdec[i];
            s0 += wv.x * dv.x; s1 += wv.y * dv.y;
            s2 += wv.z * dv.z; s3 += wv.w * dv.w;
        }
        g_dvec[b * HH + h] = (s0 + s1) + (s2 + s3);
    }
}

// ---------------------------------------------------------------------------
// Kernel B: fp16 HMMA GEMM (128h x 128n CTA tile); A via coalesced LDG of
//           prepacked fragments; B double-buffered cp.async + convert;
//           fused tanh/v epilogue + softmax
// ---------------------------------------------------------------------------
__global__ void __launch_bounds__(256, 2)
score_kernel(const float* __restrict__ adj,
             const float* __restrict__ sta,
             const float* __restrict__ dyn,
             const float* __restrict__ v,
             float* __restrict__ out)
{
    extern __shared__ __align__(16) char smem[];
    float*  Bf   = (float*)(smem + SO_BF);
    __half* Bs_h = (__half*)(smem + SO_BSH);
    float*  red  = (float*)(smem + SO_RED);
    float*  smx  = (float*)(smem + SO_SMX);

    const int tid  = threadIdx.x;
    const int lane = tid & 31;
    const int wrp  = tid >> 5;
    const int wm   = wrp >> 1;       // 0..3 (h quarter)
    const int wn   = wrp & 1;        // 0..1 (n half of 128)
    const int b  = blockIdx.y;
    const int n0 = blockIdx.x * NT;

    const float* srcs[3] = {
        adj + (size_t)b * HH * NNODE,
        sta + (size_t)b * HH * NNODE,
        dyn + (size_t)b * HH * NNODE };

    const uint32_t uBf = smem_u32(Bf);
    // B: chunk c -> Bf slot s (own commit group), zero-fill OOB
    auto stage_B = [&](int c, int s) {
        const int k0 = c * KC;
#pragma unroll
        for (int i = 0; i < 8; i++) {
            int idx = tid + i * 256;
            int krow = idx >> 5, q = idx & 31;
            int kg = k0 + krow;
            const float* src = srcs[kg >> 7] + (size_t)(kg & 127) * NNODE + n0 + q * 4;
            uint32_t doff = (uint32_t)((s * BF1 + krow * BFW + q * 4) * 4);
            uint32_t nb = (n0 + q * 4 < NNODE) ? 16u : 0u;
            CP16Z(uBf + doff, src, nb);
        }
        CP_COMMIT();
    };

    float acc[2][8][4];
#pragma unroll
    for (int mt = 0; mt < 2; mt++)
#pragma unroll
        for (int nt = 0; nt < 8; nt++)
#pragma unroll
            for (int c = 0; c < 4; c++) acc[mt][nt][c] = 0.f;

    const uint32_t bsU = smem_u32(Bs_h);
    const int bRow = (lane & 15);                  // + ks*16
    const int bCol = wn * 64 + (lane >> 4) * 8;    // + ntg*16
    const uint4* wf = g_wfrag + lane;

    stage_B(0, 0);                                  // prologue

    for (int it = 0; it < NCH; it++) {
        const int s = it & 1;
        __syncthreads();                 // prev Bs/Bf reads done
        if (it + 1 < NCH) { stage_B(it + 1, s ^ 1); CP_WAIT(1); }
        else              { CP_WAIT(0); }
        __syncthreads();                 // Bf[s] visible

        // ---- convert B fp32 -> fp16 (64 rows x 32 float4)
#pragma unroll
        for (int i = 0; i < 8; i++) {
            int idx = tid + i * 256;
            int krow = idx >> 5, q = idx & 31;
            float4 f = *(float4*)&Bf[s * BF1 + krow * BFW + q * 4];
            *(unsigned long long*)&Bs_h[krow * BPAD + q * 4] = cvt4h(f);
        }
        __syncthreads();                 // Bs ready

#pragma unroll
        for (int ks = 0; ks < 4; ks++) {
            const int kblk = it * 4 + ks;
            uint4 a0 = wf[((size_t)kblk * 8 + (wm * 2 + 0)) * 32];
            uint4 a1 = wf[((size_t)kblk * 8 + (wm * 2 + 1)) * 32];
            uint32_t ah[2][4] = {{a0.x, a0.y, a0.z, a0.w}, {a1.x, a1.y, a1.z, a1.w}};
            uint32_t bh[16];
#pragma unroll
            for (int ntg = 0; ntg < 4; ntg++) {
                uint32_t off = (uint32_t)(((ks * 16 + bRow) * BPAD + bCol + ntg * 16) * 2);
                ldsm_x4_t(bh[ntg*4+0], bh[ntg*4+1], bh[ntg*4+2], bh[ntg*4+3], bsU + off);
            }
#pragma unroll
            for (int mt = 0; mt < 2; mt++)
#pragma unroll
                for (int nt = 0; nt < 8; nt++)
                    mma16816(acc[mt][nt], ah[mt], bh[nt*2+0], bh[nt*2+1]);
        }
    }

    // ---- epilogue: tanh(acc + d) * v, reduce over h -> logits
    const int g = lane >> 2, t = lane & 3;
    const float* dp = g_dvec + b * HH;
    float d0[2], d1[2], v0[2], v1[2];
#pragma unroll
    for (int mt = 0; mt < 2; mt++) {
        int h0 = wm * 32 + mt * 16 + g;
        d0[mt] = dp[h0];     d1[mt] = dp[h0 + 8];
        v0[mt] = v[h0];      v1[mt] = v[h0 + 8];
    }
    float p[8][2];
#pragma unroll
    for (int nt = 0; nt < 8; nt++)
#pragma unroll
        for (int c = 0; c < 2; c++) {
            float sacc = 0.f;
#pragma unroll
            for (int mt = 0; mt < 2; mt++)
                sacc += v0[mt] * tanh_fast(acc[mt][nt][c]     + d0[mt])
                      + v1[mt] * tanh_fast(acc[mt][nt][c + 2] + d1[mt]);
            p[nt][c] = sacc;
        }
#pragma unroll
    for (int m = 4; m <= 16; m <<= 1)
#pragma unroll
        for (int nt = 0; nt < 8; nt++)
#pragma unroll
            for (int c = 0; c < 2; c++)
                p[nt][c] += __shfl_xor_sync(0xFFFFFFFFu, p[nt][c], m);
    if (g == 0) {
#pragma unroll
        for (int nt = 0; nt < 8; nt++)
#pragma unroll
            for (int c = 0; c < 2; c++)
                red[wm * NT + wn * 64 + nt * 8 + t * 2 + c] = p[nt][c];
    }
    __syncthreads();
    if (tid < NT) {
        float sacc = red[0*NT+tid] + red[1*NT+tid] + red[2*NT+tid] + red[3*NT+tid];
        int n = n0 + tid;
        if (n < NNODE) g_attn[b * NPAD + n] = sacc;
    }

    // ---- fused softmax: last CTA of batch b does the row softmax
    __shared__ int is_last;
    __syncthreads();              // all logit writes issued
    __threadfence();              // order writes before the count
    if (tid == 0) is_last = (atomicAdd(&g_cnt[b], 1) == NTILES - 1);
    __syncthreads();
    if (is_last) {
        const float* row = &g_attn[b * NPAD];
        float m = -INFINITY;
        for (int n = tid; n < NNODE; n += 256) m = fmaxf(m, row[n]);
        smx[tid] = m;  __syncthreads();
        for (int sred = 128; sred > 0; sred >>= 1) {
            if (tid < sred) smx[tid] = fmaxf(smx[tid], smx[tid + sred]);
            __syncthreads();
        }
        m = smx[0];  __syncthreads();

        float sum = 0.f;
        for (int n = tid; n < NNODE; n += 256) sum += __expf(row[n] - m);
        smx[tid] = sum;  __syncthreads();
        for (int sred = 128; sred > 0; sred >>= 1) {
            if (tid < sred) smx[tid] += smx[tid + sred];
            __syncthreads();
        }
        float inv = 1.f / smx[0];

        for (int n = tid; n < NNODE; n += 256)
            out[b * NNODE + n] = __expf(row[n] - m) * inv;

        __syncthreads();
        if (tid == 0) g_cnt[b] = 0;   // reset for next graph replay
    }
}

// ---------------------------------------------------------------------------
extern "C" void kernel_launch(void* const* d_in, const int* in_sizes, int n_in,
                              void* d_out, int out_size)
{
    const float* adj = (const float*)d_in[0];
    const float* sta = (const float*)d_in[1];
    const float* dyn = (const float*)d_in[2];
    const float* dec = (const float*)d_in[3];
    const float* v   = (const float*)d_in[4];
    const float* W   = (const float*)d_in[5];
    float* out = (float*)d_out;

    cudaFuncSetAttribute(score_kernel,
                         cudaFuncAttributeMaxDynamicSharedMemorySize, SMEM_SZ);

    prep_kernel<<<NKBLK * NHBLK + BB, HH>>>(W, dec);  // 448 CTAs: wfrag + dvec
    dim3 grid(NTILES, BB);                            // (8, 256)
    score_kernel<<<grid, 256, SMEM_SZ>>>(adj, sta, dyn, v, out);
}